// round 3
// baseline (speedup 1.0000x reference)
#include <cuda_runtime.h>
#include <cstdint>

// ---------------- problem constants ----------------
#define NB      16          // batch / splits
#define INC     64          // input channels
#define OUTC    64          // output channels
#define HW      128         // input H=W
#define OW      126         // output H=W (VALID 3x3)
#define FC      512
#define GROUPS  4
#define OPG     9232        // CNN_PARA / GROUPS
#define IPG     128         // FMN1 / GROUPS
#define CNNP    36928       // IN*OUT*9 + OUT

// ---------------- scratch (no allocs allowed) ----------------
__device__ float g_h2[NB * FC];
__device__ float g_wb[NB * CNNP];

// ---------------- f32x2 helpers (sm_103a packed fp32) ----------------
__device__ __forceinline__ unsigned long long pack_dup(float v) {
    unsigned long long r;
    unsigned int u = __float_as_uint(v);
    asm("mov.b64 %0, {%1, %1};" : "=l"(r) : "r"(u));
    return r;
}
__device__ __forceinline__ unsigned long long ffma2(unsigned long long a,
                                                    unsigned long long b,
                                                    unsigned long long c) {
    unsigned long long d;
    asm("fma.rn.f32x2 %0, %1, %2, %3;" : "=l"(d) : "l"(a), "l"(b), "l"(c));
    return d;
}
union F2U64 { float2 f; unsigned long long u; };

// ============================================================
// Kernel 1: fused 2-layer MLP. One block per sample, 512 threads.
// h2[b,t] = relu( relu(fc_in[b] @ w1.T + b1) @ w2.T + b2 )
// ============================================================
__global__ __launch_bounds__(FC) void mlp_kernel(
    const float* __restrict__ fc_in,
    const float* __restrict__ w1, const float* __restrict__ b1,
    const float* __restrict__ w2, const float* __restrict__ b2)
{
    __shared__ __align__(16) float s[FC];
    int b = blockIdx.x, t = threadIdx.x;
    s[t] = fc_in[b * FC + t];
    __syncthreads();

    const float4* s4 = reinterpret_cast<const float4*>(s);
    float acc = 0.f;
    {
        const float4* w4 = reinterpret_cast<const float4*>(w1 + (size_t)t * FC);
        #pragma unroll 8
        for (int k = 0; k < FC / 4; k++) {
            float4 wv = w4[k], sv = s4[k];
            acc += wv.x * sv.x + wv.y * sv.y + wv.z * sv.z + wv.w * sv.w;
        }
    }
    float h1 = fmaxf(acc + b1[t], 0.f);
    __syncthreads();
    s[t] = h1;
    __syncthreads();

    acc = 0.f;
    {
        const float4* w4 = reinterpret_cast<const float4*>(w2 + (size_t)t * FC);
        #pragma unroll 8
        for (int k = 0; k < FC / 4; k++) {
            float4 wv = w4[k], sv = s4[k];
            acc += wv.x * sv.x + wv.y * sv.y + wv.z * sv.z + wv.w * sv.w;
        }
    }
    g_h2[b * FC + t] = fmaxf(acc + b2[t], 0.f);
}

// ============================================================
// Kernel 2: grouped 1x1 "conv" generating wb[b, :] = relu(o + b3).
// Grid (GROUPS, ceil(OPG/256)), 256 threads. Each thread owns one output
// index j of group g and computes it for ALL 16 samples (w3 row read once).
// ============================================================
__global__ __launch_bounds__(256) void wbgen_kernel(
    const float* __restrict__ w3, const float* __restrict__ b3)
{
    __shared__ __align__(16) float4 s_h2[NB][IPG / 4];   // 8 KB
    int g = blockIdx.x;
    int j = blockIdx.y * 256 + threadIdx.x;

    for (int e = threadIdx.x; e < NB * IPG / 4; e += 256) {
        int bb = e >> 5, k = e & 31;
        s_h2[bb][k] = reinterpret_cast<const float4*>(g_h2 + bb * FC + g * IPG)[k];
    }
    __syncthreads();
    if (j >= OPG) return;

    float acc[NB];
    #pragma unroll
    for (int bb = 0; bb < NB; bb++) acc[bb] = 0.f;

    const float4* wr = reinterpret_cast<const float4*>(w3 + ((size_t)g * OPG + j) * IPG);
    for (int k = 0; k < IPG / 4; k++) {
        float4 w = wr[k];
        #pragma unroll
        for (int bb = 0; bb < NB; bb++) {
            float4 h = s_h2[bb][k];
            acc[bb] += w.x * h.x + w.y * h.y + w.z * h.z + w.w * h.w;
        }
    }
    float bias = b3[g * OPG + j];
    int col = g * OPG + j;
    #pragma unroll
    for (int bb = 0; bb < NB; bb++)
        g_wb[bb * CNNP + col] = fmaxf(acc[bb] + bias, 0.f);
}

// ============================================================
// Kernel 3: per-sample 3x3 VALID conv, f32x2 dual-oc packing.
// Block = (32x32 output tile, 8 output channels, 1 sample), 256 threads.
// Thread: 2x2 pixel micro-tile x 4 oc-pairs = 16 f32x2 accumulators.
// ============================================================
#define TOC   8
#define TILE  32
#define ITILE 34
#define IW    36    // padded smem row

__global__ __launch_bounds__(256, 2) void conv_kernel(
    const float* __restrict__ x, float* __restrict__ out)
{
    __shared__ float s_in[2][ITILE * IW];                 // 2 x 4.78 KB
    __shared__ __align__(8) float2 s_w[INC * 4 * 9];      // 18 KB, [ic][pair][tap]

    const int tid    = threadIdx.x;
    const int b      = blockIdx.z;
    const int ocg    = blockIdx.y;
    const int tileid = blockIdx.x;
    const int ty0 = (tileid >> 2) * TILE;
    const int tx0 = (tileid & 3) * TILE;

    const float* wbb = g_wb + (size_t)b * CNNP;

    // Load + pack weights: s_w[ic*36 + p*9 + tap] = {w[2p], w[2p+1]}
    for (int e = tid; e < INC * 4 * 9; e += 256) {
        int k  = e % 9;
        int pk = e / 9;
        int p  = pk & 3;
        int ic = pk >> 2;
        int oc0 = ocg * TOC + 2 * p;
        float w0 = wbb[(oc0 * INC + ic) * 9 + k];
        float w1v = wbb[((oc0 + 1) * INC + ic) * 9 + k];
        s_w[e] = make_float2(w0, w1v);
    }

    const int ty = tid >> 4, tx = tid & 15;

    // input tile loader (guards bottom/right edge: rows up to ty0+33 <= 129)
    auto load_tile = [&](int ic, int buf) {
        const float* xp = x + (((size_t)b * INC + ic) * HW) * HW;
        #pragma unroll
        for (int e = tid; e < ITILE * ITILE; e += 256) {
            int r = e / ITILE, c = e % ITILE;
            int gy = ty0 + r, gx = tx0 + c;
            float v = 0.f;
            if (gy < HW && gx < HW) v = __ldg(xp + gy * HW + gx);
            s_in[buf][r * IW + c] = v;
        }
    };

    unsigned long long acc[4][2][2];
    #pragma unroll
    for (int p = 0; p < 4; p++)
        #pragma unroll
        for (int i = 0; i < 2; i++)
            #pragma unroll
            for (int jx = 0; jx < 2; jx++) acc[p][i][jx] = 0ull;

    load_tile(0, 0);
    __syncthreads();

    for (int ic = 0; ic < INC; ic++) {
        int cur = ic & 1;
        if (ic + 1 < INC) load_tile(ic + 1, cur ^ 1);

        // gather 4x4 input patch, duplicate into both f32x2 lanes
        unsigned long long ind[4][4];
        #pragma unroll
        for (int dy = 0; dy < 4; dy++)
            #pragma unroll
            for (int dx = 0; dx < 4; dx++)
                ind[dy][dx] = pack_dup(s_in[cur][(2 * ty + dy) * IW + 2 * tx + dx]);

        const unsigned long long* wp =
            reinterpret_cast<const unsigned long long*>(s_w + ic * 36);
        #pragma unroll
        for (int p = 0; p < 4; p++) {
            #pragma unroll
            for (int ky = 0; ky < 3; ky++) {
                #pragma unroll
                for (int kx = 0; kx < 3; kx++) {
                    unsigned long long w = wp[p * 9 + ky * 3 + kx];
                    acc[p][0][0] = ffma2(ind[ky    ][kx    ], w, acc[p][0][0]);
                    acc[p][0][1] = ffma2(ind[ky    ][kx + 1], w, acc[p][0][1]);
                    acc[p][1][0] = ffma2(ind[ky + 1][kx    ], w, acc[p][1][0]);
                    acc[p][1][1] = ffma2(ind[ky + 1][kx + 1], w, acc[p][1][1]);
                }
            }
        }
        __syncthreads();
    }

    // epilogue: + bias, store (no activation on conv output)
    const int oy = ty0 + 2 * ty;
    const int ox = tx0 + 2 * tx;
    #pragma unroll
    for (int p = 0; p < 4; p++) {
        int oc = ocg * TOC + 2 * p;
        float bias0 = wbb[OUTC * INC * 9 + oc];
        float bias1 = wbb[OUTC * INC * 9 + oc + 1];
        float* o0 = out + (((size_t)b * OUTC + oc) * OW) * OW;
        float* o1 = o0 + (size_t)OW * OW;
        #pragma unroll
        for (int py = 0; py < 2; py++) {
            int y = oy + py;
            if (y >= OW) continue;
            #pragma unroll
            for (int px = 0; px < 2; px++) {
                int xo = ox + px;
                if (xo >= OW) continue;
                F2U64 cv; cv.u = acc[p][py][px];
                o0[y * OW + xo] = cv.f.x + bias0;
                o1[y * OW + xo] = cv.f.y + bias1;
            }
        }
    }
}

// ============================================================
extern "C" void kernel_launch(void* const* d_in, const int* in_sizes, int n_in,
                              void* d_out, int out_size)
{
    const float* x     = (const float*)d_in[0];
    const float* fc_in = (const float*)d_in[1];
    const float* w1    = (const float*)d_in[2];
    const float* b1    = (const float*)d_in[3];
    const float* w2    = (const float*)d_in[4];
    const float* b2    = (const float*)d_in[5];
    const float* w3    = (const float*)d_in[6];
    const float* b3    = (const float*)d_in[7];
    // d_in[8] = splits (constant 16), unused
    float* out = (float*)d_out;

    mlp_kernel<<<NB, FC>>>(fc_in, w1, b1, w2, b2);
    wbgen_kernel<<<dim3(GROUPS, (OPG + 255) / 256), 256>>>(w3, b3);
    conv_kernel<<<dim3(16, OUTC / TOC, NB), 256>>>(x, out);
}

// round 5
// speedup vs baseline: 1.4527x; 1.4527x over previous
#include <cuda_runtime.h>
#include <cstdint>

// ---------------- problem constants ----------------
#define NB      16          // batch / splits
#define INC     64          // input channels
#define OUTC    64          // output channels
#define HW      128         // input H=W
#define OW      126         // output H=W (VALID 3x3)
#define FC      512
#define GROUPS  4
#define OPG     9232        // CNN_PARA / GROUPS
#define IPG     128         // FMN1 / GROUPS
#define CNNP    36928       // IN*OUT*9 + OUT

// ---------------- scratch (no allocs allowed) ----------------
// NOTE: referenced ONLY from device code (never passed as host-side args --
// host-side &symbol is the ATS-visible host shadow, which silently corrupts).
__device__ float g_h1[NB * FC];
__device__ float g_h2[NB * FC];
__device__ float g_wb[NB * CNNP];

// ---------------- helpers ----------------
__device__ __forceinline__ unsigned long long pack_dup(float v) {
    unsigned long long r;
    unsigned int u = __float_as_uint(v);
    asm("mov.b64 %0, {%1, %1};" : "=l"(r) : "r"(u));
    return r;
}
__device__ __forceinline__ unsigned long long ffma2(unsigned long long a,
                                                    unsigned long long b,
                                                    unsigned long long c) {
    unsigned long long d;
    asm("fma.rn.f32x2 %0, %1, %2, %3;" : "=l"(d) : "l"(a), "l"(b), "l"(c));
    return d;
}
union F2U64 { float2 f; unsigned long long u; };

__device__ __forceinline__ unsigned int smem_u32(const void* p) {
    unsigned int a;
    asm("{ .reg .u64 t; cvta.to.shared.u64 t, %1; cvt.u32.u64 %0, t; }"
        : "=r"(a) : "l"(p));
    return a;
}
__device__ __forceinline__ void cp_async4(unsigned int sdst, const void* gsrc,
                                          unsigned int src_bytes) {
    asm volatile("cp.async.ca.shared.global [%0], [%1], 4, %2;"
                 :: "r"(sdst), "l"(gsrc), "r"(src_bytes));
}
__device__ __forceinline__ void cp_commit() {
    asm volatile("cp.async.commit_group;");
}
__device__ __forceinline__ void cp_wait0() {
    asm volatile("cp.async.wait_group 0;");
}

// ============================================================
// GEMV core: out[b,t] = relu(dot(in[b,:512], W[t,:512]) + bias[t])
// warp-per-output; grid = (FC/8, NB), block = 256.
// ============================================================
__device__ __forceinline__ void gemv_body(
    const float* __restrict__ in, const float* __restrict__ W,
    const float* __restrict__ bias, float* __restrict__ out)
{
    const int lane = threadIdx.x & 31;
    const int warp = threadIdx.x >> 5;
    const int b = blockIdx.y;
    const int t = blockIdx.x * 8 + warp;

    const float4* in4 = reinterpret_cast<const float4*>(in + (size_t)b * FC);
    const float4* w4  = reinterpret_cast<const float4*>(W + (size_t)t * FC);

    float s = 0.f;
    #pragma unroll
    for (int i = 0; i < 4; i++) {
        float4 a = in4[lane + 32 * i];
        float4 w = w4[lane + 32 * i];
        s += a.x * w.x + a.y * w.y + a.z * w.z + a.w * w.w;
    }
    #pragma unroll
    for (int off = 16; off > 0; off >>= 1)
        s += __shfl_xor_sync(0xffffffffu, s, off);

    if (lane == 0)
        out[(size_t)b * FC + t] = fmaxf(s + bias[t], 0.f);
}

// layer 1: fc_in (arg) -> g_h1 (device symbol)
__global__ __launch_bounds__(256) void gemv1_kernel(
    const float* __restrict__ fc_in, const float* __restrict__ w1,
    const float* __restrict__ b1)
{
    gemv_body(fc_in, w1, b1, g_h1);
}

// layer 2: g_h1 -> g_h2 (both device symbols)
__global__ __launch_bounds__(256) void gemv2_kernel(
    const float* __restrict__ w2, const float* __restrict__ b2)
{
    gemv_body(g_h1, w2, b2, g_h2);
}

// ============================================================
// Kernel 2: grouped 1x1 conv -> wb[b,:] = relu(o + b3).
// Thread owns output j of group g for ALL 16 samples.
// ============================================================
__global__ __launch_bounds__(256) void wbgen_kernel(
    const float* __restrict__ w3, const float* __restrict__ b3)
{
    __shared__ __align__(16) float4 s_h2[NB][IPG / 4];   // 8 KB
    int g = blockIdx.x;
    int j = blockIdx.y * 256 + threadIdx.x;

    for (int e = threadIdx.x; e < NB * IPG / 4; e += 256) {
        int bb = e >> 5, k = e & 31;
        s_h2[bb][k] = reinterpret_cast<const float4*>(g_h2 + bb * FC + g * IPG)[k];
    }
    __syncthreads();
    if (j >= OPG) return;

    float acc[NB];
    #pragma unroll
    for (int bb = 0; bb < NB; bb++) acc[bb] = 0.f;

    const float4* wr = reinterpret_cast<const float4*>(w3 + ((size_t)g * OPG + j) * IPG);
    #pragma unroll 4
    for (int k = 0; k < IPG / 4; k++) {
        float4 w = wr[k];
        #pragma unroll
        for (int bb = 0; bb < NB; bb++) {
            float4 h = s_h2[bb][k];
            acc[bb] += w.x * h.x + w.y * h.y + w.z * h.z + w.w * h.w;
        }
    }
    float bias = b3[g * OPG + j];
    int col = g * OPG + j;
    #pragma unroll
    for (int bb = 0; bb < NB; bb++)
        g_wb[bb * CNNP + col] = fmaxf(acc[bb] + bias, 0.f);
}

// ============================================================
// Kernel 3: per-sample 3x3 VALID conv, f32x2 dual-oc packing.
// Block = (32x32 output tile, 8 oc, 1 sample), 256 threads.
// cp.async double-buffered tile loads, 2 input channels per round.
// ============================================================
#define TOC   8
#define TILE  32
#define ITILE 34
#define IW    36            // padded smem row (floats)
#define ICB   2             // input channels per round
#define NRND  (INC / ICB)   // 32

__global__ __launch_bounds__(256, 2) void conv_kernel(
    const float* __restrict__ x, float* __restrict__ out)
{
    __shared__ float s_in[2][ICB][ITILE * IW];            // 19.1 KB
    __shared__ __align__(8) float2 s_w[INC * 4 * 9];      // 18 KB, [ic][pair][tap]

    const int tid    = threadIdx.x;
    const int b      = blockIdx.z;
    const int ocg    = blockIdx.y;
    const int tileid = blockIdx.x;
    const int ty0 = (tileid >> 2) * TILE;
    const int tx0 = (tileid & 3) * TILE;

    const float* wbb = g_wb + (size_t)b * CNNP;

    // Load + pack weights once: s_w[ic*36 + p*9 + tap] = {w[oc0], w[oc0+1]}
    for (int e = tid; e < INC * 4 * 9; e += 256) {
        int k  = e % 9;
        int pk = e / 9;
        int p  = pk & 3;
        int ic = pk >> 2;
        int oc0 = ocg * TOC + 2 * p;
        float w0  = wbb[(oc0 * INC + ic) * 9 + k];
        float w1v = wbb[((oc0 + 1) * INC + ic) * 9 + k];
        s_w[e] = make_float2(w0, w1v);
    }

    const int ty = tid >> 4, tx = tid & 15;

    // async tile loader for an ic pair -> buffer buf (ZFILL on OOB)
    auto load_pair = [&](int r, int buf) {
        #pragma unroll
        for (int sub = 0; sub < ICB; sub++) {
            int ic = r * ICB + sub;
            const float* xp = x + (((size_t)b * INC + ic) * HW) * HW;
            #pragma unroll
            for (int e = tid; e < ITILE * ITILE; e += 256) {
                int rr = e / ITILE, cc = e % ITILE;
                int gy = ty0 + rr, gx = tx0 + cc;
                unsigned int sdst = smem_u32(&s_in[buf][sub][rr * IW + cc]);
                unsigned int ok = (gy < HW && gx < HW) ? 4u : 0u;
                cp_async4(sdst, xp + gy * HW + gx, ok);
            }
        }
        cp_commit();
    };

    unsigned long long acc[4][2][2];
    #pragma unroll
    for (int p = 0; p < 4; p++)
        #pragma unroll
        for (int i = 0; i < 2; i++)
            #pragma unroll
            for (int jx = 0; jx < 2; jx++) acc[p][i][jx] = 0ull;

    load_pair(0, 0);
    cp_wait0();
    __syncthreads();

    for (int r = 0; r < NRND; r++) {
        const int cur = r & 1;
        if (r + 1 < NRND) load_pair(r + 1, cur ^ 1);

        #pragma unroll
        for (int sub = 0; sub < ICB; sub++) {
            const int ic = r * ICB + sub;
            const float* sin = s_in[cur][sub];

            unsigned long long ind[4][4];
            #pragma unroll
            for (int dy = 0; dy < 4; dy++)
                #pragma unroll
                for (int dx = 0; dx < 4; dx++)
                    ind[dy][dx] = pack_dup(sin[(2 * ty + dy) * IW + 2 * tx + dx]);

            const unsigned long long* wp =
                reinterpret_cast<const unsigned long long*>(s_w + ic * 36);
            #pragma unroll
            for (int p = 0; p < 4; p++) {
                #pragma unroll
                for (int ky = 0; ky < 3; ky++) {
                    #pragma unroll
                    for (int kx = 0; kx < 3; kx++) {
                        unsigned long long w = wp[p * 9 + ky * 3 + kx];
                        acc[p][0][0] = ffma2(ind[ky    ][kx    ], w, acc[p][0][0]);
                        acc[p][0][1] = ffma2(ind[ky    ][kx + 1], w, acc[p][0][1]);
                        acc[p][1][0] = ffma2(ind[ky + 1][kx    ], w, acc[p][1][0]);
                        acc[p][1][1] = ffma2(ind[ky + 1][kx + 1], w, acc[p][1][1]);
                    }
                }
            }
        }

        cp_wait0();
        __syncthreads();
    }

    // epilogue: + bias, store
    const int oy = ty0 + 2 * ty;
    const int ox = tx0 + 2 * tx;
    #pragma unroll
    for (int p = 0; p < 4; p++) {
        int oc = ocg * TOC + 2 * p;
        float bias0 = wbb[OUTC * INC * 9 + oc];
        float bias1 = wbb[OUTC * INC * 9 + oc + 1];
        float* o0 = out + (((size_t)b * OUTC + oc) * OW) * OW;
        float* o1 = o0 + (size_t)OW * OW;
        #pragma unroll
        for (int py = 0; py < 2; py++) {
            int y = oy + py;
            if (y >= OW) continue;
            #pragma unroll
            for (int px = 0; px < 2; px++) {
                int xo = ox + px;
                if (xo >= OW) continue;
                F2U64 cv; cv.u = acc[p][py][px];
                o0[y * OW + xo] = cv.f.x + bias0;
                o1[y * OW + xo] = cv.f.y + bias1;
            }
        }
    }
}

// ============================================================
extern "C" void kernel_launch(void* const* d_in, const int* in_sizes, int n_in,
                              void* d_out, int out_size)
{
    const float* x     = (const float*)d_in[0];
    const float* fc_in = (const float*)d_in[1];
    const float* w1    = (const float*)d_in[2];
    const float* b1    = (const float*)d_in[3];
    const float* w2    = (const float*)d_in[4];
    const float* b2    = (const float*)d_in[5];
    const float* w3    = (const float*)d_in[6];
    const float* b3    = (const float*)d_in[7];
    float* out = (float*)d_out;

    gemv1_kernel<<<dim3(FC / 8, NB), 256>>>(fc_in, w1, b1);
    gemv2_kernel<<<dim3(FC / 8, NB), 256>>>(w2, b2);
    wbgen_kernel<<<dim3(GROUPS, (OPG + 255) / 256), 256>>>(w3, b3);
    conv_kernel<<<dim3(16, OUTC / TOC, NB), 256>>>(x, out);
}

// round 6
// speedup vs baseline: 1.5851x; 1.0912x over previous
#include <cuda_runtime.h>
#include <cstdint>

// ---------------- problem constants ----------------
#define NB      16          // batch / splits
#define INC     64          // input channels
#define OUTC    64          // output channels
#define HW      128         // input H=W
#define OW      126         // output H=W (VALID 3x3)
#define FC      512
#define GROUPS  4
#define OPG     9232        // CNN_PARA / GROUPS
#define IPG     128         // FMN1 / GROUPS
#define CNNP    36928       // IN*OUT*9 + OUT

// ---------------- scratch (no allocs allowed) ----------------
// Referenced ONLY from device code (host-side &symbol is the ATS shadow).
__device__ float g_h1[NB * FC];
__device__ float g_h2[NB * FC];
__device__ float g_wb[NB * CNNP];

// ---------------- helpers ----------------
__device__ __forceinline__ unsigned long long pack_dup(float v) {
    unsigned long long r;
    unsigned int u = __float_as_uint(v);
    asm("mov.b64 %0, {%1, %1};" : "=l"(r) : "r"(u));
    return r;
}
__device__ __forceinline__ unsigned long long ffma2(unsigned long long a,
                                                    unsigned long long b,
                                                    unsigned long long c) {
    unsigned long long d;
    asm("fma.rn.f32x2 %0, %1, %2, %3;" : "=l"(d) : "l"(a), "l"(b), "l"(c));
    return d;
}
union F2U64 { float2 f; unsigned long long u; };

__device__ __forceinline__ unsigned int smem_u32(const void* p) {
    unsigned int a;
    asm("{ .reg .u64 t; cvta.to.shared.u64 t, %1; cvt.u32.u64 %0, t; }"
        : "=r"(a) : "l"(p));
    return a;
}
__device__ __forceinline__ void cp_async4(unsigned int sdst, const void* gsrc,
                                          unsigned int src_bytes) {
    asm volatile("cp.async.ca.shared.global [%0], [%1], 4, %2;"
                 :: "r"(sdst), "l"(gsrc), "r"(src_bytes));
}
__device__ __forceinline__ void cp_commit() {
    asm volatile("cp.async.commit_group;");
}
__device__ __forceinline__ void cp_wait0() {
    asm volatile("cp.async.wait_group 0;");
}

// ============================================================
// GEMV core: out[b,t] = relu(dot(in[b,:512], W[t,:512]) + bias[t])
// warp-per-output; grid = (FC/8, NB), block = 256.
// ============================================================
__device__ __forceinline__ void gemv_body(
    const float* __restrict__ in, const float* __restrict__ W,
    const float* __restrict__ bias, float* __restrict__ out)
{
    const int lane = threadIdx.x & 31;
    const int warp = threadIdx.x >> 5;
    const int b = blockIdx.y;
    const int t = blockIdx.x * 8 + warp;

    const float4* in4 = reinterpret_cast<const float4*>(in + (size_t)b * FC);
    const float4* w4  = reinterpret_cast<const float4*>(W + (size_t)t * FC);

    float s = 0.f;
    #pragma unroll
    for (int i = 0; i < 4; i++) {
        float4 a = in4[lane + 32 * i];
        float4 w = w4[lane + 32 * i];
        s += a.x * w.x + a.y * w.y + a.z * w.z + a.w * w.w;
    }
    #pragma unroll
    for (int off = 16; off > 0; off >>= 1)
        s += __shfl_xor_sync(0xffffffffu, s, off);

    if (lane == 0)
        out[(size_t)b * FC + t] = fmaxf(s + bias[t], 0.f);
}

__global__ __launch_bounds__(256) void gemv1_kernel(
    const float* __restrict__ fc_in, const float* __restrict__ w1,
    const float* __restrict__ b1)
{
    gemv_body(fc_in, w1, b1, g_h1);
}

__global__ __launch_bounds__(256) void gemv2_kernel(
    const float* __restrict__ w2, const float* __restrict__ b2)
{
    gemv_body(g_h1, w2, b2, g_h2);
}

// ============================================================
// Kernel 2: grouped 1x1 conv -> wb[b,:] = relu(o + b3).
// ============================================================
__global__ __launch_bounds__(256) void wbgen_kernel(
    const float* __restrict__ w3, const float* __restrict__ b3)
{
    __shared__ __align__(16) float4 s_h2[NB][IPG / 4];   // 8 KB
    int g = blockIdx.x;
    int j = blockIdx.y * 256 + threadIdx.x;

    for (int e = threadIdx.x; e < NB * IPG / 4; e += 256) {
        int bb = e >> 5, k = e & 31;
        s_h2[bb][k] = reinterpret_cast<const float4*>(g_h2 + bb * FC + g * IPG)[k];
    }
    __syncthreads();
    if (j >= OPG) return;

    float acc[NB];
    #pragma unroll
    for (int bb = 0; bb < NB; bb++) acc[bb] = 0.f;

    const float4* wr = reinterpret_cast<const float4*>(w3 + ((size_t)g * OPG + j) * IPG);
    #pragma unroll 4
    for (int k = 0; k < IPG / 4; k++) {
        float4 w = wr[k];
        #pragma unroll
        for (int bb = 0; bb < NB; bb++) {
            float4 h = s_h2[bb][k];
            acc[bb] += w.x * h.x + w.y * h.y + w.z * h.z + w.w * h.w;
        }
    }
    float bias = b3[g * OPG + j];
    int col = g * OPG + j;
    #pragma unroll
    for (int bb = 0; bb < NB; bb++)
        g_wb[bb * CNNP + col] = fmaxf(acc[bb] + bias, 0.f);
}

// ============================================================
// Kernel 3: per-sample 3x3 VALID conv, f32x2 dual-oc packing.
// Block = 128 threads = 8(tx) x 16(ty); thread covers 2 rows x 4 cols
// of a 32x32 output tile, for 4 oc-pairs (8 oc). 288 FFMA2 per ic
// per thread vs 44 LDS (8 vectorized input + 36 broadcast weight).
// ============================================================
#define TOC   8
#define TILE  32
#define ITILE 34
#define IW    36            // padded smem row (floats); 36*4B % 16 == 0
#define ICB   2             // input channels per round
#define NRND  (INC / ICB)   // 32

__global__ __launch_bounds__(128, 3) void conv_kernel(
    const float* __restrict__ x, float* __restrict__ out)
{
    __shared__ __align__(16) float s_in[2][ICB][ITILE * IW];  // 19.1 KB
    __shared__ __align__(8) float2 s_w[INC * 4 * 9];          // 18 KB

    const int tid    = threadIdx.x;
    const int b      = blockIdx.z;
    const int ocg    = blockIdx.y;
    const int tileid = blockIdx.x;
    const int ty0 = (tileid >> 2) * TILE;
    const int tx0 = (tileid & 3) * TILE;

    const float* wbb = g_wb + (size_t)b * CNNP;

    // Pack weights once: s_w[ic*36 + p*9 + tap] = {w[oc0], w[oc0+1]}
    for (int e = tid; e < INC * 4 * 9; e += 128) {
        int k  = e % 9;
        int pk = e / 9;
        int p  = pk & 3;
        int ic = pk >> 2;
        int oc0 = ocg * TOC + 2 * p;
        float w0  = wbb[(oc0 * INC + ic) * 9 + k];
        float w1v = wbb[((oc0 + 1) * INC + ic) * 9 + k];
        s_w[e] = make_float2(w0, w1v);
    }

    const int ty = tid >> 3;        // 0..15  -> rows 2ty, 2ty+1
    const int tx = tid & 7;         // 0..7   -> cols 4tx..4tx+3

    // async tile loader for an ic pair -> buffer buf (ZFILL on OOB)
    auto load_pair = [&](int r, int buf) {
        #pragma unroll
        for (int sub = 0; sub < ICB; sub++) {
            int ic = r * ICB + sub;
            const float* xp = x + (((size_t)b * INC + ic) * HW) * HW;
            #pragma unroll
            for (int e = tid; e < ITILE * ITILE; e += 128) {
                int rr = e / ITILE, cc = e % ITILE;
                int gy = ty0 + rr, gx = tx0 + cc;
                unsigned int sdst = smem_u32(&s_in[buf][sub][rr * IW + cc]);
                unsigned int ok = (gy < HW && gx < HW) ? 4u : 0u;
                cp_async4(sdst, xp + gy * HW + gx, ok);
            }
        }
        cp_commit();
    };

    unsigned long long acc[4][2][4];
    #pragma unroll
    for (int p = 0; p < 4; p++)
        #pragma unroll
        for (int i = 0; i < 2; i++)
            #pragma unroll
            for (int jx = 0; jx < 4; jx++) acc[p][i][jx] = 0ull;

    load_pair(0, 0);
    cp_wait0();
    __syncthreads();

    for (int r = 0; r < NRND; r++) {
        const int cur = r & 1;
        if (r + 1 < NRND) load_pair(r + 1, cur ^ 1);

        #pragma unroll
        for (int sub = 0; sub < ICB; sub++) {
            const int ic = r * ICB + sub;
            const float* sin = s_in[cur][sub];

            // 4 rows x 6 cols input patch: LDS.128 + LDS.64 per row
            unsigned long long ind[4][6];
            #pragma unroll
            for (int dy = 0; dy < 4; dy++) {
                const float* rowp = sin + (2 * ty + dy) * IW + 4 * tx;
                float4 v = *reinterpret_cast<const float4*>(rowp);
                float2 u = *reinterpret_cast<const float2*>(rowp + 4);
                ind[dy][0] = pack_dup(v.x);
                ind[dy][1] = pack_dup(v.y);
                ind[dy][2] = pack_dup(v.z);
                ind[dy][3] = pack_dup(v.w);
                ind[dy][4] = pack_dup(u.x);
                ind[dy][5] = pack_dup(u.y);
            }

            const unsigned long long* wp =
                reinterpret_cast<const unsigned long long*>(s_w + ic * 36);
            #pragma unroll
            for (int p = 0; p < 4; p++) {
                #pragma unroll
                for (int ky = 0; ky < 3; ky++) {
                    #pragma unroll
                    for (int kx = 0; kx < 3; kx++) {
                        unsigned long long w = wp[p * 9 + ky * 3 + kx];
                        #pragma unroll
                        for (int py = 0; py < 2; py++) {
                            #pragma unroll
                            for (int px = 0; px < 4; px++)
                                acc[p][py][px] =
                                    ffma2(ind[py + ky][px + kx], w, acc[p][py][px]);
                        }
                    }
                }
            }
        }

        cp_wait0();
        __syncthreads();
    }

    // epilogue: + bias, store as float2 pairs (even-aligned; exact edge guard)
    const int oy = ty0 + 2 * ty;
    const int ox = tx0 + 4 * tx;
    #pragma unroll
    for (int p = 0; p < 4; p++) {
        int oc = ocg * TOC + 2 * p;
        float bias0 = wbb[OUTC * INC * 9 + oc];
        float bias1 = wbb[OUTC * INC * 9 + oc + 1];
        float* o0 = out + (((size_t)b * OUTC + oc) * OW) * OW;
        float* o1 = o0 + (size_t)OW * OW;
        #pragma unroll
        for (int py = 0; py < 2; py++) {
            int y = oy + py;
            if (y >= OW) continue;
            #pragma unroll
            for (int px2 = 0; px2 < 2; px2++) {
                int xo = ox + 2 * px2;
                if (xo >= OW) continue;   // pairs are even-aligned; OW even
                F2U64 a; a.u = acc[p][py][2 * px2];
                F2U64 c; c.u = acc[p][py][2 * px2 + 1];
                float2 r0 = make_float2(a.f.x + bias0, c.f.x + bias0);
                float2 r1 = make_float2(a.f.y + bias1, c.f.y + bias1);
                *reinterpret_cast<float2*>(o0 + (size_t)y * OW + xo) = r0;
                *reinterpret_cast<float2*>(o1 + (size_t)y * OW + xo) = r1;
            }
        }
    }
}

// ============================================================
extern "C" void kernel_launch(void* const* d_in, const int* in_sizes, int n_in,
                              void* d_out, int out_size)
{
    const float* x     = (const float*)d_in[0];
    const float* fc_in = (const float*)d_in[1];
    const float* w1    = (const float*)d_in[2];
    const float* b1    = (const float*)d_in[3];
    const float* w2    = (const float*)d_in[4];
    const float* b2    = (const float*)d_in[5];
    const float* w3    = (const float*)d_in[6];
    const float* b3    = (const float*)d_in[7];
    float* out = (float*)d_out;

    gemv1_kernel<<<dim3(FC / 8, NB), 256>>>(fc_in, w1, b1);
    gemv2_kernel<<<dim3(FC / 8, NB), 256>>>(w2, b2);
    wbgen_kernel<<<dim3(GROUPS, (OPG + 255) / 256), 256>>>(w3, b3);
    conv_kernel<<<dim3(16, OUTC / TOC, NB), 128>>>(x, out);
}

// round 8
// speedup vs baseline: 3.5504x; 2.2399x over previous
#include <cuda_runtime.h>
#include <cuda_fp16.h>
#include <cstdint>

// ---------------- problem constants ----------------
#define NB      16
#define INC     64
#define OUTC    64
#define HW      128
#define OW      126
#define FC      512
#define GROUPS  4
#define OPG     9232
#define IPG     128
#define CNNP    36928
#define NWCOL   36864

// ---------------- scratch (device-code refs only) ----------------
__device__ float g_h1[NB * FC];
__device__ float g_h2[NB * FC];
// pre-split, pre-swizzled weights: [b][ky][part][kx][oc][ic(swizzled units)]
__device__ __half g_wm[NB][3][2][3][64][64];
__device__ float g_bias[NB * OUTC];

// smem layout (dynamic)
#define SM_W      0        // 49152 B : [part][kx][oc][64 halves, swizzled 16B units]
#define SM_X      49152    // 40960 B : [part][160 c-rows][64 halves, swizzled]
#define SM_BIAS   90112    // 256 B
#define SM_TOTAL  90624
#define XPART     20480    // bytes per part tile of s_x

// ---------------- PTX helpers ----------------
__device__ __forceinline__ unsigned int smem_u32(const void* p) {
    unsigned int a;
    asm("{ .reg .u64 t; cvta.to.shared.u64 t, %1; cvt.u32.u64 %0, t; }"
        : "=r"(a) : "l"(p));
    return a;
}
__device__ __forceinline__ void cp_async16(unsigned int sdst, const void* gsrc) {
    asm volatile("cp.async.cg.shared.global [%0], [%1], 16;" :: "r"(sdst), "l"(gsrc));
}
__device__ __forceinline__ void cp_commit() { asm volatile("cp.async.commit_group;"); }
__device__ __forceinline__ void cp_wait0()  { asm volatile("cp.async.wait_group 0;"); }

__device__ __forceinline__ void ldsm_x4(uint32_t& r0, uint32_t& r1, uint32_t& r2,
                                        uint32_t& r3, uint32_t addr) {
    asm volatile("ldmatrix.sync.aligned.m8n8.x4.shared.b16 {%0,%1,%2,%3}, [%4];"
                 : "=r"(r0), "=r"(r1), "=r"(r2), "=r"(r3) : "r"(addr));
}
__device__ __forceinline__ void mma16816(float* c, const uint32_t* a,
                                         uint32_t b0, uint32_t b1) {
    asm volatile(
        "mma.sync.aligned.m16n8k16.row.col.f32.f16.f16.f32 "
        "{%0,%1,%2,%3}, {%4,%5,%6,%7}, {%8,%9}, {%0,%1,%2,%3};"
        : "+f"(c[0]), "+f"(c[1]), "+f"(c[2]), "+f"(c[3])
        : "r"(a[0]), "r"(a[1]), "r"(a[2]), "r"(a[3]), "r"(b0), "r"(b1));
}
__device__ __forceinline__ uint32_t pack_h2(__half a, __half b) {
    return (uint32_t)__half_as_ushort(a) | ((uint32_t)__half_as_ushort(b) << 16);
}

// ============================================================
// Kernel 1: GEMV + bias + relu, warp-per-output.
// ============================================================
__device__ __forceinline__ void gemv_body(
    const float* __restrict__ in, const float* __restrict__ W,
    const float* __restrict__ bias, float* __restrict__ out)
{
    const int lane = threadIdx.x & 31;
    const int warp = threadIdx.x >> 5;
    const int b = blockIdx.y;
    const int t = blockIdx.x * 8 + warp;

    const float4* in4 = reinterpret_cast<const float4*>(in + (size_t)b * FC);
    const float4* w4  = reinterpret_cast<const float4*>(W + (size_t)t * FC);

    float s = 0.f;
    #pragma unroll
    for (int i = 0; i < 4; i++) {
        float4 a = in4[lane + 32 * i];
        float4 w = w4[lane + 32 * i];
        s += a.x * w.x + a.y * w.y + a.z * w.z + a.w * w.w;
    }
    #pragma unroll
    for (int off = 16; off > 0; off >>= 1)
        s += __shfl_xor_sync(0xffffffffu, s, off);
    if (lane == 0)
        out[(size_t)b * FC + t] = fmaxf(s + bias[t], 0.f);
}
__global__ __launch_bounds__(256) void gemv1_kernel(
    const float* __restrict__ fc_in, const float* __restrict__ w1,
    const float* __restrict__ b1) { gemv_body(fc_in, w1, b1, g_h1); }
__global__ __launch_bounds__(256) void gemv2_kernel(
    const float* __restrict__ w2, const float* __restrict__ b2) { gemv_body(g_h1, w2, b2, g_h2); }

// ============================================================
// Kernel 2: wbgen -> hi/lo-split, unit-swizzled weight images + bias.
// ============================================================
__global__ __launch_bounds__(256) void wbgen_kernel(
    const float* __restrict__ w3, const float* __restrict__ b3)
{
    __shared__ __align__(16) float4 s_h2[NB][IPG / 4];
    int g = blockIdx.x;
    int j = blockIdx.y * 256 + threadIdx.x;

    for (int e = threadIdx.x; e < NB * IPG / 4; e += 256) {
        int bb = e >> 5, k = e & 31;
        s_h2[bb][k] = reinterpret_cast<const float4*>(g_h2 + bb * FC + g * IPG)[k];
    }
    __syncthreads();
    if (j >= OPG) return;

    float acc[NB];
    #pragma unroll
    for (int bb = 0; bb < NB; bb++) acc[bb] = 0.f;

    const float4* wr = reinterpret_cast<const float4*>(w3 + ((size_t)g * OPG + j) * IPG);
    #pragma unroll 4
    for (int k = 0; k < IPG / 4; k++) {
        float4 w = wr[k];
        #pragma unroll
        for (int bb = 0; bb < NB; bb++) {
            float4 h = s_h2[bb][k];
            acc[bb] += w.x * h.x + w.y * h.y + w.z * h.z + w.w * h.w;
        }
    }
    float bias = b3[g * OPG + j];
    int col = g * OPG + j;

    if (col < NWCOL) {
        // col = oc*576 + ic*9 + ky*3 + kx
        int oc = col / 576;
        int r  = col - oc * 576;
        int ic = r / 9;
        int kt = r - ic * 9;
        int ky = kt / 3;
        int kx = kt - ky * 3;
        int ic_sw = (((ic >> 3) ^ (oc & 7)) << 3) | (ic & 7);
        #pragma unroll
        for (int bb = 0; bb < NB; bb++) {
            float w = fmaxf(acc[bb] + bias, 0.f);
            __half hi = __float2half_rn(w);
            __half lo = __float2half_rn(w - __half2float(hi));
            g_wm[bb][ky][0][kx][oc][ic_sw] = hi;
            g_wm[bb][ky][1][kx][oc][ic_sw] = lo;
        }
    } else {
        int oc = col - NWCOL;
        #pragma unroll
        for (int bb = 0; bb < NB; bb++)
            g_bias[bb * OUTC + oc] = fmaxf(acc[bb] + bias, 0.f);
    }
}

// ============================================================
// Kernel 3: HMMA implicit-GEMM conv.
// CTA = (output row oy, sample b). D[oc 64][px 128] over K=576.
// 8 warps = 2(oc) x 4(px); warp tile 32oc x 32px; fp16 hi/lo 3-MMA split.
// ============================================================
__global__ __launch_bounds__(256, 2) void conv_mma(
    const float* __restrict__ x, float* __restrict__ out)
{
    extern __shared__ char smem[];
    const uint32_t sb = smem_u32(smem);
    const int tid = threadIdx.x;
    const int w   = tid >> 5;
    const int L   = tid & 31;
    const int oy  = blockIdx.x;      // 0..125
    const int b   = blockIdx.y;      // 0..15

    float* s_bias = reinterpret_cast<float*>(smem + SM_BIAS);
    if (tid < OUTC) s_bias[tid] = g_bias[b * OUTC + tid];

    float acc[2][4][4];
    #pragma unroll
    for (int mt = 0; mt < 2; mt++)
        #pragma unroll
        for (int nt = 0; nt < 4; nt++)
            #pragma unroll
            for (int i = 0; i < 4; i++) acc[mt][nt][i] = 0.f;

    const int ocw = (w & 1) * 32;    // warp oc base
    const int pxw = (w >> 1) * 32;   // warp px base
    const int gq  = L >> 3;          // ldmatrix lane group 0..3
    const int gi  = L & 7;

    for (int ky = 0; ky < 3; ky++) {
        __syncthreads();   // prior MMAs done before overwriting tiles

        // ---- stage weights: flat cp.async of pre-swizzled image (49152 B) ----
        {
            const char* src = reinterpret_cast<const char*>(&g_wm[b][ky][0][0][0][0]);
            #pragma unroll
            for (int e = tid; e < 49152 / 16; e += 256)
                cp_async16(sb + SM_W + e * 16, src + e * 16);
            cp_commit();
        }

        // ---- stage x row (transpose + hi/lo split): s_x[part][c][ic] ----
        {
            const int y = oy + ky;   // 0..127, always in range
            const float* xr = x + (size_t)b * INC * HW * HW + (size_t)y * HW;
            const int ic0 = w * 8;   // warp owns 8 ic rows
            #pragma unroll
            for (int k = 0; k < 5; k++) {
                int c  = k * 32 + L;           // 0..159
                int cc = c < HW ? c : HW - 1;  // clamp (cols >=128 feed masked px only)
                float v[8];
                #pragma unroll
                for (int i = 0; i < 8; i++)
                    v[i] = __ldg(xr + (size_t)(ic0 + i) * HW * HW + cc);
                uint32_t hi[4], lo[4];
                #pragma unroll
                for (int i = 0; i < 4; i++) {
                    __half h0 = __float2half_rn(v[2 * i]);
                    __half h1 = __float2half_rn(v[2 * i + 1]);
                    __half l0 = __float2half_rn(v[2 * i]     - __half2float(h0));
                    __half l1 = __float2half_rn(v[2 * i + 1] - __half2float(h1));
                    hi[i] = pack_h2(h0, h1);
                    lo[i] = pack_h2(l0, l1);
                }
                uint32_t p = (uint32_t)(w ^ (c & 7));      // unit swizzle
                uint32_t off = (uint32_t)c * 128u + p * 16u;
                *reinterpret_cast<uint4*>(smem + SM_X + off) =
                    make_uint4(hi[0], hi[1], hi[2], hi[3]);
                *reinterpret_cast<uint4*>(smem + SM_X + XPART + off) =
                    make_uint4(lo[0], lo[1], lo[2], lo[3]);
            }
        }

        cp_wait0();
        __syncthreads();

        // ---- MMA: kx(3) x ksteps(4 of ic16) ----
        for (int kx = 0; kx < 3; kx++) {
            #pragma unroll
            for (int ks = 0; ks < 4; ks++) {
                const int ub = ks * 2;   // base 16B-unit (= ic0/8)

                // A fragments: weights [oc][ic], non-trans ldmatrix
                uint32_t a[2][2][4];     // [mt][part][4]
                #pragma unroll
                for (int mt = 0; mt < 2; mt++) {
                    #pragma unroll
                    for (int part = 0; part < 2; part++) {
                        int row = ocw + mt * 16 + (gq & 1) * 8 + gi;
                        int u   = ub + (gq >> 1);
                        uint32_t addr = sb + SM_W +
                            (uint32_t)(((part * 3 + kx) * 64 + row) * 128 +
                                       ((u ^ (row & 7)) * 16));
                        ldsm_x4(a[mt][part][0], a[mt][part][1],
                                a[mt][part][2], a[mt][part][3], addr);
                    }
                }
                // B fragments: x [c][ic], non-trans ldmatrix; kx shifts the row
                uint32_t bb[2][2][4];    // [part][np][4] = b0(n0),b1(n0),b0(n1),b1(n1)
                #pragma unroll
                for (int part = 0; part < 2; part++) {
                    #pragma unroll
                    for (int np = 0; np < 2; np++) {
                        int c = pxw + np * 16 + kx + (gq >> 1) * 8 + gi;
                        int u = ub + (gq & 1);
                        uint32_t addr = sb + SM_X + part * XPART +
                            (uint32_t)(c * 128 + ((u ^ (c & 7)) * 16));
                        ldsm_x4(bb[part][np][0], bb[part][np][1],
                                bb[part][np][2], bb[part][np][3], addr);
                    }
                }
                // 24 HMMA: hi*hi + hi*lo + lo*hi
                #pragma unroll
                for (int mt = 0; mt < 2; mt++) {
                    #pragma unroll
                    for (int nt = 0; nt < 4; nt++) {
                        int np = nt >> 1, s = (nt & 1) * 2;
                        mma16816(acc[mt][nt], a[mt][0], bb[0][np][s], bb[0][np][s + 1]);
                        mma16816(acc[mt][nt], a[mt][0], bb[1][np][s], bb[1][np][s + 1]);
                        mma16816(acc[mt][nt], a[mt][1], bb[0][np][s], bb[0][np][s + 1]);
                    }
                }
            }
        }
    }

    // ---- epilogue: + bias, store float2 (px pairs even-aligned) ----
    const int r4 = L >> 2;
    const int q  = (L & 3) * 2;
    #pragma unroll
    for (int mt = 0; mt < 2; mt++) {
        #pragma unroll
        for (int nt = 0; nt < 4; nt++) {
            int oc = ocw + mt * 16 + r4;
            int px = pxw + nt * 8 + q;
            if (px < OW) {
                float bi0 = s_bias[oc];
                float bi1 = s_bias[oc + 8];
                float* o = out + (((size_t)(b * OUTC + oc)) * OW + oy) * OW + px;
                float2 v0 = make_float2(acc[mt][nt][0] + bi0, acc[mt][nt][1] + bi0);
                float2 v1 = make_float2(acc[mt][nt][2] + bi1, acc[mt][nt][3] + bi1);
                *reinterpret_cast<float2*>(o) = v0;
                *reinterpret_cast<float2*>(o + (size_t)8 * OW * OW) = v1;
            }
        }
    }
}

// ============================================================
extern "C" void kernel_launch(void* const* d_in, const int* in_sizes, int n_in,
                              void* d_out, int out_size)
{
    const float* x     = (const float*)d_in[0];
    const float* fc_in = (const float*)d_in[1];
    const float* w1    = (const float*)d_in[2];
    const float* b1    = (const float*)d_in[3];
    const float* w2    = (const float*)d_in[4];
    const float* b2    = (const float*)d_in[5];
    const float* w3    = (const float*)d_in[6];
    const float* b3    = (const float*)d_in[7];
    float* out = (float*)d_out;

    cudaFuncSetAttribute(conv_mma, cudaFuncAttributeMaxDynamicSharedMemorySize, SM_TOTAL);

    gemv1_kernel<<<dim3(FC / 8, NB), 256>>>(fc_in, w1, b1);
    gemv2_kernel<<<dim3(FC / 8, NB), 256>>>(w2, b2);
    wbgen_kernel<<<dim3(GROUPS, (OPG + 255) / 256), 256>>>(w3, b3);
    conv_mma<<<dim3(OW, NB), 256, SM_TOTAL>>>(x, out);
}